// round 17
// baseline (speedup 1.0000x reference)
#include <cuda_runtime.h>
#include <cuda_bf16.h>
#include <cuda_fp16.h>
#include <math.h>

// Problem constants (fixed by the reference)
#define B_  4
#define C_  64
#define O_  64
#define H_  128
#define W_  128
#define K2_ 9
#define HW_ (H_*W_)
#define CK_ (C_*K2_)          // 576

// ---------------- scratch (no allocations allowed) ----------------
// Main weight in mma.sync B-fragment layout (fp16):
// idx = ((t*4 + kc)*8 + nt)*32 + lane
__device__ uint2 g_wB[9*4*8*32];
// Offset-conv weight, B-fragment layout, fp16, N padded to 32:
// idx = ((t*4 + kc)*4 + nt)*32 + lane
__device__ uint2 g_wOB[9*4*4*32];
// x repacked channel-major fp16: pixel-major, 64 ch contiguous = 128B/pixel
__device__ uint4 g_xc[B_*HW_*8];

__device__ __forceinline__ unsigned smem_u32(const void* p) {
    unsigned a;
    asm("{ .reg .u64 t; cvta.to.shared.u64 t, %1; cvt.u32.u64 %0, t; }"
        : "=r"(a) : "l"(p));
    return a;
}

// ---------------- kernel 0: prep (tiled x transpose + weight fragments) ----------------
__global__ void __launch_bounds__(256)
prep(const float* __restrict__ x, const float* __restrict__ w_om,
     const float* __restrict__ weight) {
    __shared__ float tile[64][33];

    const int tid = threadIdx.x;
    const int g32 = blockIdx.x;             // 32-px group, 512 per batch
    const int b   = g32 >> 9;
    const int p0  = (g32 & 511) * 32;

    const float* xb = x + (size_t)b*C_*HW_ + p0;
    #pragma unroll
    for (int i = tid; i < 64*32; i += 256) {
        const int c = i >> 5, px = i & 31;
        tile[c][px] = xb[(size_t)c*HW_ + px];
    }
    __syncthreads();

    {
        const int px = tid >> 3, ch = tid & 7;
        unsigned w[4];
        #pragma unroll
        for (int j = 0; j < 4; j++) {
            __half2 h = __floats2half2_rn(tile[ch*8 + 2*j][px],
                                          tile[ch*8 + 2*j + 1][px]);
            w[j] = *reinterpret_cast<unsigned*>(&h);
        }
        uint4 o; o.x = w[0]; o.y = w[1]; o.z = w[2]; o.w = w[3];
        g_xc[(size_t)(b*HW_ + p0 + px)*8 + ch] = o;
    }

    const int gid = blockIdx.x*256 + tid;

    if (gid < 9216) {
        int i = gid;
        int t    = i / 1024;
        int r    = i - t*1024;
        int kc   = r >> 8;
        int r2   = r & 255;
        int nt   = r2 >> 5;
        int lane = r2 & 31;
        int n  = nt*8 + (lane >> 2);
        int kb = (lane & 3)*2;
        unsigned hv[2];
        #pragma unroll
        for (int u = 0; u < 2; u++) {
            int c0 = kc*16 + kb + u*8;
            float w0 = weight[n*CK_ + c0*9 + t];
            float w1 = weight[n*CK_ + (c0+1)*9 + t];
            __half2 h = __floats2half2_rn(w0, w1);
            hv[u] = *reinterpret_cast<unsigned*>(&h);
        }
        uint2 hi; hi.x = hv[0]; hi.y = hv[1];
        g_wB[i] = hi;
    }

    if (gid < 4608) {
        int i = gid;
        int t    = i / 512;
        int r    = i - t*512;
        int kc   = r >> 7;
        int r2   = r & 127;
        int nt   = r2 >> 5;
        int lane = r2 & 31;
        int n  = nt*8 + (lane >> 2);
        int kb = (lane & 3)*2;
        unsigned hv[2];
        #pragma unroll
        for (int u = 0; u < 2; u++) {
            int c0 = kc*16 + kb + u*8;
            float w0 = (n < 27) ? w_om[n*CK_ + c0*9 + t]     : 0.f;
            float w1 = (n < 27) ? w_om[n*CK_ + (c0+1)*9 + t] : 0.f;
            __half2 h = __floats2half2_rn(w0, w1);
            hv[u] = *reinterpret_cast<unsigned*>(&h);
        }
        uint2 hi; hi.x = hv[0]; hi.y = hv[1];
        g_wOB[i] = hi;
    }
}

// ---------------- deform helpers ----------------
struct TapCoef {
    int o00, o01, o10, o11;
    float c00, c01, c10, c11;
};

__device__ __forceinline__ TapCoef tap_coeffs(float dy, float dx, float m,
                                              int t, int yq, int xq) {
    TapCoef r;
    const int ky = t / 3, kx = t - ky*3;
    const float sy = dy + (float)(ky + yq - 1);
    const float sx = dx + (float)(kx + xq - 1);

    const float y0f = floorf(sy), x0f = floorf(sx);
    const int iy0 = (int)y0f, ix0 = (int)x0f;
    const float wy1 = sy - y0f, wx1 = sx - x0f;
    const float wy0 = 1.f - wy1, wx0 = 1.f - wx1;

    const bool py0 = (iy0   >= 0) && (iy0   < H_);
    const bool py1 = (iy0+1 >= 0) && (iy0+1 < H_);
    const bool qx0 = (ix0   >= 0) && (ix0   < W_);
    const bool qx1 = (ix0+1 >= 0) && (ix0+1 < W_);

    const int y0c = min(max(iy0,   0), H_-1);
    const int y1c = min(max(iy0+1, 0), H_-1);
    const int x0c = min(max(ix0,   0), W_-1);
    const int x1c = min(max(ix0+1, 0), W_-1);

    r.o00 = y0c*W_ + x0c;  r.o01 = y0c*W_ + x1c;
    r.o10 = y1c*W_ + x0c;  r.o11 = y1c*W_ + x1c;

    r.c00 = (py0 && qx0) ? wy0*wx0*m : 0.f;
    r.c01 = (py0 && qx1) ? wy0*wx1*m : 0.f;
    r.c10 = (py1 && qx0) ? wy1*wx0*m : 0.f;
    r.c11 = (py1 && qx1) ? wy1*wx1*m : 0.f;
    return r;
}

__device__ __forceinline__ void gather_tap(const uint4* xcb, unsigned char* sAbuf,
                                           int wp, int lane, const TapCoef& tc) {
    const int chunk = lane & 7;
    #pragma unroll
    for (int it = 0; it < 8; it++) {
        const int j = it*4 + (lane >> 3);       // pixel idx 0..31 in warp
        const int p0 = __shfl_sync(0xffffffffu, tc.o00, j);
        const int p1 = __shfl_sync(0xffffffffu, tc.o01, j);
        const int p2 = __shfl_sync(0xffffffffu, tc.o10, j);
        const int p3 = __shfl_sync(0xffffffffu, tc.o11, j);
        const float k0 = __shfl_sync(0xffffffffu, tc.c00, j);
        const float k1 = __shfl_sync(0xffffffffu, tc.c01, j);
        const float k2 = __shfl_sync(0xffffffffu, tc.c10, j);
        const float k3 = __shfl_sync(0xffffffffu, tc.c11, j);

        const __half2 hk0 = __float2half2_rn(k0);
        const __half2 hk1 = __float2half2_rn(k1);
        const __half2 hk2 = __float2half2_rn(k2);
        const __half2 hk3 = __float2half2_rn(k3);

        const uint4 w0 = xcb[p0*8 + chunk];
        const uint4 w1 = xcb[p1*8 + chunk];
        const uint4 w2 = xcb[p2*8 + chunk];
        const uint4 w3 = xcb[p3*8 + chunk];

        unsigned outw[4];
        #pragma unroll
        for (int q = 0; q < 4; q++) {
            const __half2 f0 = *(const __half2*)&(&w0.x)[q];
            const __half2 f1 = *(const __half2*)&(&w1.x)[q];
            const __half2 f2 = *(const __half2*)&(&w2.x)[q];
            const __half2 f3 = *(const __half2*)&(&w3.x)[q];
            __half2 v = __hmul2(hk0, f0);
            v = __hfma2(hk1, f1, v);
            v = __hfma2(hk2, f2, v);
            v = __hfma2(hk3, f3, v);
            outw[q] = *reinterpret_cast<const unsigned*>(&v);
        }
        uint4 ov; ov.x = outw[0]; ov.y = outw[1]; ov.z = outw[2]; ov.w = outw[3];
        const int prow = wp*32 + j;
        const unsigned off = (unsigned)(prow*128 + 16*(chunk ^ (prow & 7)));
        *(uint4*)(sAbuf + off) = ov;
    }
}

// ---------------- kernel 1: FUSED offset-conv + deform GEMM ----------------
// Phase 1: offset conv (N=32) over the CTA's 256-px tile, pipelined shifted-A,
//          B from g_wOB (L1). Offsets+mask parked in SMEM (sOff, 27/px).
// Phase 2: deform implicit GEMM exactly as R16, coeffs read from sOff.
#define SOFF   65536
#define SMEM_F (65536 + 27648)      // 2 A-buffers + sOff = 93184

__global__ void __launch_bounds__(256, 2)
fused(const float* __restrict__ b_om, const float* __restrict__ bias,
      float* __restrict__ out) {
    extern __shared__ unsigned char smem[];     // bufs @0/32768, sOff @65536
    float* sOff = (float*)(smem + SOFF);        // [256][27]

    const int tid  = threadIdx.x;
    const int lane = tid & 31;
    const int wp   = tid >> 5;          // warp 0..7 -> pixels wp*32..+31
    const int b    = blockIdx.x >> 6;
    const int tile = blockIdx.x & 63;   // 2-row tile
    const uint4* xcb = g_xc + (size_t)b*HW_*8;

    const unsigned sAu = smem_u32(smem);
    const int chunk = lane & 7;

    const int gpix = tile*256 + tid;
    const int yq   = gpix >> 7, xq = gpix & 127;

    // ================= Phase 1: offset conv =================
    {
        float aoc[2][4][4];
        #pragma unroll
        for (int ti = 0; ti < 2; ti++)
            #pragma unroll
            for (int nt = 0; nt < 4; nt++)
                #pragma unroll
                for (int j = 0; j < 4; j++) aoc[ti][nt][j] = 0.f;

        // shifted-A gather for tap t into buf
        auto gather_shift = [&](int t, unsigned char* buf) {
            const int ky = t / 3, kx = t - ky*3;
            #pragma unroll
            for (int it = 0; it < 8; it++) {
                const int j = it*4 + (lane >> 3);
                const int prow = wp*32 + j;
                const int gp = tile*256 + prow;
                const int yy = (gp >> 7) + ky - 1;
                const int xx = (gp & 127) + kx - 1;
                uint4 v = make_uint4(0u, 0u, 0u, 0u);
                if (yy >= 0 && yy < H_ && xx >= 0 && xx < W_)
                    v = xcb[(yy*W_ + xx)*8 + chunk];
                const unsigned off = (unsigned)(prow*128 + 16*(chunk ^ (prow & 7)));
                *(uint4*)(buf + off) = v;
            }
        };

        gather_shift(0, smem);
        __syncthreads();

        #pragma unroll 1
        for (int t = 0; t < 9; t++) {
            if (t < 8) gather_shift(t + 1, smem + ((t + 1) & 1)*32768);

            const unsigned abase = sAu + (unsigned)((t & 1)*32768);
            #pragma unroll
            for (int kc = 0; kc < 4; kc++) {
                const uint2* gB = g_wOB + ((t*4 + kc)*4)*32;
                uint2 bh[4];
                #pragma unroll
                for (int nt = 0; nt < 4; nt++) bh[nt] = gB[nt*32 + lane];
                #pragma unroll
                for (int ti = 0; ti < 2; ti++) {
                    const int prow = wp*32 + ti*16 + (lane & 15);
                    const int chnk = 2*kc + (lane >> 4);
                    const unsigned aoff = abase + (unsigned)(prow*128 + 16*(chnk ^ (prow & 7)));
                    unsigned a0, a1, a2, a3;
                    asm volatile("ldmatrix.sync.aligned.m8n8.x4.shared.b16 {%0,%1,%2,%3}, [%4];"
                                 : "=r"(a0), "=r"(a1), "=r"(a2), "=r"(a3) : "r"(aoff));
                    #pragma unroll
                    for (int nt = 0; nt < 4; nt++) {
                        float* d = aoc[ti][nt];
                        asm volatile(
                            "mma.sync.aligned.m16n8k16.row.col.f32.f16.f16.f32 "
                            "{%0,%1,%2,%3}, {%4,%5,%6,%7}, {%8,%9}, {%0,%1,%2,%3};"
                            : "+f"(d[0]), "+f"(d[1]), "+f"(d[2]), "+f"(d[3])
                            : "r"(a0), "r"(a1), "r"(a2), "r"(a3), "r"(bh[nt].x), "r"(bh[nt].y));
                    }
                }
            }
            __syncthreads();
        }

        // stage D into stride-33 SMEM (A buffers are dead now)
        float* sD = (float*)smem;
        {
            const int r0 = lane >> 2;
            const int cp = (lane & 3)*2;
            #pragma unroll
            for (int ti = 0; ti < 2; ti++) {
                const int row = wp*32 + ti*16 + r0;
                #pragma unroll
                for (int nt = 0; nt < 4; nt++) {
                    const int col = nt*8 + cp;
                    float* d = aoc[ti][nt];
                    sD[row*33 + col]           = d[0];
                    sD[row*33 + col + 1]       = d[1];
                    sD[(row + 8)*33 + col]     = d[2];
                    sD[(row + 8)*33 + col + 1] = d[3];
                }
            }
        }
        __syncthreads();

        // per-pixel bias + sigmoid -> sOff[px][27]
        {
            const float* row = sD + tid*33;
            float* o = sOff + tid*27;
            #pragma unroll
            for (int k = 0; k < 9; k++) {
                o[k]      = row[2*k]     + b_om[2*k];
                o[9 + k]  = row[2*k + 1] + b_om[2*k + 1];
                float ml  = row[18 + k]  + b_om[18 + k];
                o[18 + k] = 1.f / (1.f + __expf(-ml));
            }
        }
        __syncthreads();
    }

    // ================= Phase 2: deform GEMM =================
    float acc[2][8][4];
    #pragma unroll
    for (int ti = 0; ti < 2; ti++)
        #pragma unroll
        for (int nt = 0; nt < 8; nt++)
            #pragma unroll
            for (int j = 0; j < 4; j++) acc[ti][nt][j] = 0.f;

    const float* myOff = sOff + tid*27;

    // prologue: gather tap 0 into buffer 0 (overwrites sD staging)
    {
        TapCoef tc = tap_coeffs(myOff[0], myOff[9], myOff[18], 0, yq, xq);
        gather_tap(xcb, smem, wp, lane, tc);
    }
    __syncthreads();

    #pragma unroll 1
    for (int t = 0; t < 9; t++) {
        if (t < 8) {
            TapCoef tc = tap_coeffs(myOff[t+1], myOff[9 + t+1], myOff[18 + t+1],
                                    t + 1, yq, xq);
            gather_tap(xcb, smem + ((t + 1) & 1)*32768, wp, lane, tc);
        }

        const unsigned abase = sAu + (unsigned)((t & 1)*32768);
        #pragma unroll
        for (int kc = 0; kc < 4; kc++) {
            const uint2* gB = g_wB + (t*4 + kc)*256;
            uint2 bf[8];
            #pragma unroll
            for (int nt = 0; nt < 8; nt++) bf[nt] = gB[nt*32 + lane];
            #pragma unroll
            for (int ti = 0; ti < 2; ti++) {
                const int prow = wp*32 + ti*16 + (lane & 15);
                const int chnk = 2*kc + (lane >> 4);
                const unsigned aoff = abase + (unsigned)(prow*128 + 16*(chnk ^ (prow & 7)));
                unsigned a0, a1, a2, a3;
                asm volatile("ldmatrix.sync.aligned.m8n8.x4.shared.b16 {%0,%1,%2,%3}, [%4];"
                             : "=r"(a0), "=r"(a1), "=r"(a2), "=r"(a3) : "r"(aoff));

                #pragma unroll
                for (int nt = 0; nt < 8; nt++) {
                    float* d = acc[ti][nt];
                    asm volatile(
                        "mma.sync.aligned.m16n8k16.row.col.f32.f16.f16.f32 "
                        "{%0,%1,%2,%3}, {%4,%5,%6,%7}, {%8,%9}, {%0,%1,%2,%3};"
                        : "+f"(d[0]), "+f"(d[1]), "+f"(d[2]), "+f"(d[3])
                        : "r"(a0), "r"(a1), "r"(a2), "r"(a3), "r"(bf[nt].x), "r"(bf[nt].y));
                }
            }
        }

        __syncthreads();
    }

    // ---- epilogue ----
    {
        const int r0 = lane >> 2;
        const int cp = (lane & 3)*2;
        #pragma unroll
        for (int ti = 0; ti < 2; ti++) {
            float* obase = out + (size_t)(b*O_)*HW_ + tile*256 + wp*32 + ti*16;
            #pragma unroll
            for (int nt = 0; nt < 8; nt++) {
                const int o = nt*8 + cp;
                const float bi0 = bias[o], bi1 = bias[o+1];
                obase[(size_t)o*HW_     + r0    ] = acc[ti][nt][0] + bi0;
                obase[(size_t)(o+1)*HW_ + r0    ] = acc[ti][nt][1] + bi1;
                obase[(size_t)o*HW_     + r0 + 8] = acc[ti][nt][2] + bi0;
                obase[(size_t)(o+1)*HW_ + r0 + 8] = acc[ti][nt][3] + bi1;
            }
        }
    }
}

// ---------------- launch ----------------
extern "C" void kernel_launch(void* const* d_in, const int* in_sizes, int n_in,
                              void* d_out, int out_size) {
    const float* x      = (const float*)d_in[0];
    const float* w_om   = (const float*)d_in[1];
    const float* b_om   = (const float*)d_in[2];
    const float* weight = (const float*)d_in[3];
    const float* bias   = (const float*)d_in[4];
    float* out = (float*)d_out;

    cudaFuncSetAttribute(fused, cudaFuncAttributeMaxDynamicSharedMemorySize, SMEM_F);
    cudaFuncSetAttribute(fused, cudaFuncAttributePreferredSharedMemoryCarveout, 100);

    prep<<<2048, 256>>>(x, w_om, weight);
    fused<<<256, 256, SMEM_F>>>(b_om, bias, out);
}